// round 1
// baseline (speedup 1.0000x reference)
#include <cuda_runtime.h>

// MinibatchDiscrimination: x[32,512,256], T[256,512] -> out[32,512,288]
// M = x @ T  (per sample: 512 values = 32 kernels x 16 dims)
// a[n,k1,d] = sum_{k2} |M[n,k2,d] - M[n,k1,d]|   (sum over k2 BEFORE exp!)
// feat[n,k1] = sum_d exp(-a[n,k1,d])
// out = concat(x, feat)

#define NSAMP   16384   // 32*512
#define FDIM    256
#define NCOLS   512     // 32 kernels * 16 dims
#define NK      32
#define KD      16
#define OUTF    288
#define SPB     16      // samples per block
#define KCH     32      // K-chunk for GEMM
#define NT      256

// dynamic smem layout (floats):
//   xs : SPB*FDIM      = 4096   (16 KB)
//   Ts : KCH*NCOLS     = 16384  (64 KB)
//   Ms : SPB*NCOLS     = 8192   (32 KB)
#define SMEM_FLOATS (SPB*FDIM + KCH*NCOLS + SPB*NCOLS)
#define SMEM_BYTES  (SMEM_FLOATS * 4)

extern __shared__ float smem_dyn[];

__global__ void __launch_bounds__(NT) mbd_kernel(
    const float* __restrict__ x,
    const float* __restrict__ T,
    float* __restrict__ out)
{
    float* xs = smem_dyn;                 // [SPB][FDIM]
    float* Ts = xs + SPB * FDIM;          // [KCH][NCOLS]
    float* Ms = Ts + KCH * NCOLS;         // [SPB][NCOLS]

    const int t = threadIdx.x;
    const int b = blockIdx.x;
    const long sbase = (long)b * SPB;     // first sample of this block

    // ---- load x tile: 16*256 = 4096 floats = 1024 float4 ----
    {
        const float4* xg = (const float4*)(x + sbase * FDIM);
        float4* xs4 = (float4*)xs;
        #pragma unroll
        for (int i = 0; i < 4; i++) xs4[t + i * NT] = xg[t + i * NT];
    }

    // ---- GEMM: acc[4 samples][8 cols] per thread ----
    const int cg = t & 63;   // col group: cols cg*8 .. cg*8+7
    const int sg = t >> 6;   // sample group: samples sg*4 .. sg*4+3

    float acc[4][8];
    #pragma unroll
    for (int s = 0; s < 4; s++)
        #pragma unroll
        for (int j = 0; j < 8; j++) acc[s][j] = 0.f;

    for (int kk = 0; kk < FDIM; kk += KCH) {
        __syncthreads();   // previous chunk's compute done (and xs ready on iter 0)
        // load T chunk: 32 rows x 512 cols = 16384 floats = 4096 float4
        {
            const float4* Tg = (const float4*)(T + (long)kk * NCOLS);
            float4* Ts4 = (float4*)Ts;
            #pragma unroll
            for (int i = 0; i < 16; i++) Ts4[t + i * NT] = Tg[t + i * NT];
        }
        __syncthreads();

        #pragma unroll
        for (int k = 0; k < KCH; k += 4) {
            float4 xv[4];
            #pragma unroll
            for (int s = 0; s < 4; s++)
                xv[s] = *(const float4*)&xs[(sg * 4 + s) * FDIM + kk + k];

            #pragma unroll
            for (int k2 = 0; k2 < 4; k2++) {
                const float4 t0 = *(const float4*)&Ts[(k + k2) * NCOLS + cg * 8];
                const float4 t1 = *(const float4*)&Ts[(k + k2) * NCOLS + cg * 8 + 4];
                #pragma unroll
                for (int s = 0; s < 4; s++) {
                    const float xe = (k2 == 0) ? xv[s].x :
                                     (k2 == 1) ? xv[s].y :
                                     (k2 == 2) ? xv[s].z : xv[s].w;
                    acc[s][0] += xe * t0.x;
                    acc[s][1] += xe * t0.y;
                    acc[s][2] += xe * t0.z;
                    acc[s][3] += xe * t0.w;
                    acc[s][4] += xe * t1.x;
                    acc[s][5] += xe * t1.y;
                    acc[s][6] += xe * t1.z;
                    acc[s][7] += xe * t1.w;
                }
            }
        }
    }

    // ---- store M to smem ----
    #pragma unroll
    for (int s = 0; s < 4; s++) {
        float* mp = &Ms[(sg * 4 + s) * NCOLS + cg * 8];
        *(float4*)mp       = make_float4(acc[s][0], acc[s][1], acc[s][2], acc[s][3]);
        *(float4*)(mp + 4) = make_float4(acc[s][4], acc[s][5], acc[s][6], acc[s][7]);
    }
    __syncthreads();

    // ---- copy x tile to output (coalesced float4) ----
    {
        const float4* xs4 = (const float4*)xs;
        #pragma unroll
        for (int i = 0; i < 4; i++) {
            const int idx = t + i * NT;        // float4 index 0..1023
            const int s   = idx >> 6;          // 64 float4 per sample row
            const int f4  = idx & 63;
            *(float4*)&out[(sbase + s) * OUTF + f4 * 4] = xs4[idx];
        }
    }

    // ---- pairwise L1 + exp features ----
    // warp w handles samples 2w and 2w+1; lane = k1
    const int w = t >> 5;
    const int lane = t & 31;

    #pragma unroll
    for (int si = 0; si < 2; si++) {
        const int s = w * 2 + si;
        const float* Mrow = &Ms[s * NCOLS];

        // this lane's own 16 values: M[s][k1=lane][d], d=0..15
        float v1[16];
        {
            const float4 a0 = *(const float4*)&Mrow[lane * KD + 0];
            const float4 a1 = *(const float4*)&Mrow[lane * KD + 4];
            const float4 a2 = *(const float4*)&Mrow[lane * KD + 8];
            const float4 a3 = *(const float4*)&Mrow[lane * KD + 12];
            v1[0]=a0.x; v1[1]=a0.y; v1[2]=a0.z; v1[3]=a0.w;
            v1[4]=a1.x; v1[5]=a1.y; v1[6]=a1.z; v1[7]=a1.w;
            v1[8]=a2.x; v1[9]=a2.y; v1[10]=a2.z; v1[11]=a2.w;
            v1[12]=a3.x; v1[13]=a3.y; v1[14]=a3.z; v1[15]=a3.w;
        }

        float a[16];
        #pragma unroll
        for (int d = 0; d < 16; d++) a[d] = 0.f;

        // loop over k2; all lanes read same addresses -> smem broadcast
        #pragma unroll 4
        for (int k2 = 0; k2 < NK; k2++) {
            const float4 m0 = *(const float4*)&Mrow[k2 * KD + 0];
            const float4 m1 = *(const float4*)&Mrow[k2 * KD + 4];
            const float4 m2 = *(const float4*)&Mrow[k2 * KD + 8];
            const float4 m3 = *(const float4*)&Mrow[k2 * KD + 12];
            a[0]  += fabsf(m0.x - v1[0]);
            a[1]  += fabsf(m0.y - v1[1]);
            a[2]  += fabsf(m0.z - v1[2]);
            a[3]  += fabsf(m0.w - v1[3]);
            a[4]  += fabsf(m1.x - v1[4]);
            a[5]  += fabsf(m1.y - v1[5]);
            a[6]  += fabsf(m1.z - v1[6]);
            a[7]  += fabsf(m1.w - v1[7]);
            a[8]  += fabsf(m2.x - v1[8]);
            a[9]  += fabsf(m2.y - v1[9]);
            a[10] += fabsf(m2.z - v1[10]);
            a[11] += fabsf(m2.w - v1[11]);
            a[12] += fabsf(m3.x - v1[12]);
            a[13] += fabsf(m3.y - v1[13]);
            a[14] += fabsf(m3.z - v1[14]);
            a[15] += fabsf(m3.w - v1[15]);
        }

        float facc = 0.f;
        #pragma unroll
        for (int d = 0; d < 16; d++)
            facc += __expf(-a[d]);   // underflows cleanly to 0 for large a

        out[(sbase + s) * OUTF + FDIM + lane] = facc;
    }
}

extern "C" void kernel_launch(void* const* d_in, const int* in_sizes, int n_in,
                              void* d_out, int out_size)
{
    const float* x = (const float*)d_in[0];
    const float* T = (const float*)d_in[1];
    // defensive: identify by size (x has 4,194,304 elems; T has 131,072)
    if (n_in >= 2 && in_sizes[0] < in_sizes[1]) {
        const float* tmp = x; x = T; T = tmp;
    }
    float* out = (float*)d_out;

    static bool attr_done = false;
    if (!attr_done) {
        cudaFuncSetAttribute(mbd_kernel,
                             cudaFuncAttributeMaxDynamicSharedMemorySize,
                             SMEM_BYTES);
        attr_done = true;
    }

    mbd_kernel<<<NSAMP / SPB, NT, SMEM_BYTES>>>(x, T, out);
}

// round 9
// speedup vs baseline: 4.0900x; 4.0900x over previous
#include <cuda_runtime.h>
#include <cuda_bf16.h>
#include <stdint.h>

// MinibatchDiscrimination: x[32,512,256] f32, T[256,512] f32 -> out[32,512,288] f32
// M = x @ T (bf16 tensor-core GEMM), a[n,k1,d] = sum_k2 |M[n,k2,d]-M[n,k1,d]|,
// feat[n,k1] = sum_d exp(-a) (underflows to 0; guarded), out = concat(x, feat).

#define NSAMP   16384
#define FDIM    256
#define NCOLS   512
#define NK      32
#define KD      16
#define OUTF    288
#define SPB     32          // samples per block
#define NBLK    (NSAMP/SPB) // 512
#define NT      256
#define KC      32          // K chunk

// smem (halfs): xs[32][264], Ts[32][520], Ms[32][520]
#define XST 264
#define TST 520
#define MST 520
#define XS_OFF 0
#define TS_OFF (32*XST)
#define MS_OFF (TS_OFF + KC*TST)
#define SMEM_HALFS (MS_OFF + 32*MST)
#define SMEM_BYTES (SMEM_HALFS*2)

__device__ __nv_bfloat16 g_Tbf[FDIM * NCOLS];   // pre-converted T (256 KB)

__global__ void convT_kernel(const float* __restrict__ T) {
    int i = blockIdx.x * blockDim.x + threadIdx.x;   // float4 index, 0..32767
    float4 v = ((const float4*)T)[i];
    __nv_bfloat162 p0 = __floats2bfloat162_rn(v.x, v.y);
    __nv_bfloat162 p1 = __floats2bfloat162_rn(v.z, v.w);
    *(__nv_bfloat162*)&g_Tbf[i * 4]     = p0;
    *(__nv_bfloat162*)&g_Tbf[i * 4 + 2] = p1;
}

__device__ __forceinline__ unsigned int smem_addr(const void* p) {
    return (unsigned int)__cvta_generic_to_shared(p);
}

__device__ __forceinline__ void ldmatrix_x4(unsigned int* r, unsigned int addr) {
    asm volatile("ldmatrix.sync.aligned.m8n8.x4.shared.b16 {%0,%1,%2,%3}, [%4];"
                 : "=r"(r[0]), "=r"(r[1]), "=r"(r[2]), "=r"(r[3]) : "r"(addr));
}
__device__ __forceinline__ void ldmatrix_x2_trans(unsigned int* r, unsigned int addr) {
    asm volatile("ldmatrix.sync.aligned.m8n8.x2.trans.shared.b16 {%0,%1}, [%2];"
                 : "=r"(r[0]), "=r"(r[1]) : "r"(addr));
}
__device__ __forceinline__ void mma_bf16(float* c, const unsigned int* a, const unsigned int* b) {
    asm volatile("mma.sync.aligned.m16n8k16.row.col.f32.bf16.bf16.f32 "
                 "{%0,%1,%2,%3}, {%4,%5,%6,%7}, {%8,%9}, {%0,%1,%2,%3};"
                 : "+f"(c[0]), "+f"(c[1]), "+f"(c[2]), "+f"(c[3])
                 : "r"(a[0]), "r"(a[1]), "r"(a[2]), "r"(a[3]), "r"(b[0]), "r"(b[1]));
}

extern __shared__ __nv_bfloat16 sm[];

__global__ void __launch_bounds__(NT, 2) mbd_kernel(
    const float* __restrict__ x,
    float* __restrict__ out)
{
    __nv_bfloat16* xs = sm + XS_OFF;
    __nv_bfloat16* Ts = sm + TS_OFF;
    __nv_bfloat16* Ms = sm + MS_OFF;

    const int t = threadIdx.x;
    const int warp = t >> 5;
    const int lane = t & 31;
    const long sbase = (long)blockIdx.x * SPB;

    // ---- stage x: gmem -> out (copy) and -> xs (bf16) ----
    {
        const float4* xg = (const float4*)(x + sbase * FDIM);
        #pragma unroll
        for (int i = 0; i < 8; i++) {
            int idx = t + i * NT;         // 0..2047 float4
            int s = idx >> 6, c4 = idx & 63;
            float4 v = xg[idx];
            *(float4*)&out[(sbase + s) * OUTF + c4 * 4] = v;
            *(__nv_bfloat162*)&xs[s * XST + c4 * 4]     = __floats2bfloat162_rn(v.x, v.y);
            *(__nv_bfloat162*)&xs[s * XST + c4 * 4 + 2] = __floats2bfloat162_rn(v.z, v.w);
        }
    }

    // ---- GEMM: warp w computes rows 0..31 x cols [w*64, w*64+64) ----
    const int n0 = warp * 64;
    float acc[2][8][4];
    #pragma unroll
    for (int mt = 0; mt < 2; mt++)
        #pragma unroll
        for (int nt = 0; nt < 8; nt++)
            #pragma unroll
            for (int j = 0; j < 4; j++) acc[mt][nt][j] = 0.f;

    const int arow = lane & 15;
    const int acg  = lane >> 4;

    for (int ch = 0; ch < FDIM / KC; ch++) {
        __syncthreads();   // xs ready (ch=0) / prev chunk consumed (ch>0)
        // stage T chunk (bf16, already converted): 32x512 halfs = 2048 uint4
        {
            const uint4* Tg = (const uint4*)(g_Tbf + (long)ch * KC * NCOLS);
            #pragma unroll
            for (int i = 0; i < 8; i++) {
                int idx = t + i * NT;
                int r = idx >> 6, c = idx & 63;
                *(uint4*)&Ts[r * TST + c * 8] = Tg[idx];
            }
        }
        __syncthreads();

        #pragma unroll
        for (int ks = 0; ks < KC / 16; ks++) {
            const int kl = ks * 16;
            unsigned int a[2][4];
            #pragma unroll
            for (int mt = 0; mt < 2; mt++)
                ldmatrix_x4(a[mt], smem_addr(&xs[(mt * 16 + arow) * XST + ch * KC + kl + acg * 8]));
            #pragma unroll
            for (int nt = 0; nt < 8; nt++) {
                unsigned int b[2];
                ldmatrix_x2_trans(b, smem_addr(&Ts[(kl + arow) * TST + n0 + nt * 8]));
                mma_bf16(acc[0][nt], a[0], b);
                mma_bf16(acc[1][nt], a[1], b);
            }
        }
    }

    // ---- store M (bf16) to smem ----
    __syncthreads();
    {
        const int r = lane >> 2, c = (lane & 3) * 2;
        #pragma unroll
        for (int mt = 0; mt < 2; mt++)
            #pragma unroll
            for (int nt = 0; nt < 8; nt++) {
                *(__nv_bfloat162*)&Ms[(mt * 16 + r)     * MST + n0 + nt * 8 + c] =
                    __floats2bfloat162_rn(acc[mt][nt][0], acc[mt][nt][1]);
                *(__nv_bfloat162*)&Ms[(mt * 16 + r + 8) * MST + n0 + nt * 8 + c] =
                    __floats2bfloat162_rn(acc[mt][nt][2], acc[mt][nt][3]);
            }
    }
    __syncthreads();

    // ---- pairwise L1 + guarded exp; warp w handles samples w*4..w*4+3, lane = k1 ----
    #pragma unroll
    for (int si = 0; si < 4; si++) {
        const int s = warp * 4 + si;
        const __nv_bfloat16* Mrow = &Ms[s * MST];

        __align__(16) __nv_bfloat162 v[8];
        *(uint4*)&v[0] = *(const uint4*)&Mrow[lane * KD];
        *(uint4*)&v[4] = *(const uint4*)&Mrow[lane * KD + 8];

        __nv_bfloat162 a8[8];
        const __nv_bfloat162 z2 = __floats2bfloat162_rn(0.f, 0.f);
        #pragma unroll
        for (int j = 0; j < 8; j++) a8[j] = z2;

        #pragma unroll 4
        for (int k2 = 0; k2 < NK; k2++) {
            __align__(16) __nv_bfloat162 m[8];
            *(uint4*)&m[0] = *(const uint4*)&Mrow[k2 * KD];       // broadcast
            *(uint4*)&m[4] = *(const uint4*)&Mrow[k2 * KD + 8];
            #pragma unroll
            for (int j = 0; j < 8; j++)
                a8[j] = __hadd2(a8[j], __habs2(__hsub2(m[j], v[j])));
        }

        float av[16];
        float mn = 1e30f;
        #pragma unroll
        for (int j = 0; j < 8; j++) {
            float2 f = __bfloat1622float2(a8[j]);
            av[2 * j] = f.x; av[2 * j + 1] = f.y;
            mn = fminf(mn, fminf(f.x, f.y));
        }

        float facc = 0.f;
        if (__any_sync(0xffffffffu, mn < 100.0f)) {   // exp(-100)=3.7e-44: faithful, ~never taken
            #pragma unroll
            for (int d = 0; d < 16; d++)
                if (av[d] < 100.0f) facc += __expf(-av[d]);
        }
        out[(sbase + s) * OUTF + FDIM + lane] = facc;
    }
}

extern "C" void kernel_launch(void* const* d_in, const int* in_sizes, int n_in,
                              void* d_out, int out_size)
{
    const float* x = (const float*)d_in[0];
    const float* T = (const float*)d_in[1];
    if (n_in >= 2 && in_sizes[0] < in_sizes[1]) {
        const float* tmp = x; x = T; T = tmp;
    }
    float* out = (float*)d_out;

    cudaFuncSetAttribute(mbd_kernel,
                         cudaFuncAttributeMaxDynamicSharedMemorySize,
                         SMEM_BYTES);

    convT_kernel<<<(FDIM * NCOLS / 4) / NT, NT>>>(T);
    mbd_kernel<<<NBLK, NT, SMEM_BYTES>>>(x, out);
}